// round 2
// baseline (speedup 1.0000x reference)
#include <cuda_runtime.h>
#include <math.h>

// ---------------------------------------------------------------------------
// Encoder: 3 stages, each = strided conv (k4,s2,p1) + ConvGRU (k5,p2), T=12, B=8
// Stage1: 1->64  @128^2 -> 64^2   GRU C=64  @64^2
// Stage2: 64->128 @64^2 -> 32^2   GRU C=128 @32^2
// Stage3: 128->128 @32^2 -> 16^2  GRU C=128 @16^2
// Output: concat(h1, h2, h3) final states.
// ---------------------------------------------------------------------------

#define S1_N (8*64*64*64)    // 2097152
#define S2_N (8*128*32*32)   // 1048576
#define S3_N (8*128*16*16)   // 262144

__device__ float g_h1[S1_N], g_x1[S1_N], g_z1[S1_N], g_rh1[S1_N];
__device__ float g_h2[S2_N], g_x2[S2_N], g_z2[S2_N], g_rh2[S2_N];
__device__ float g_h3[S3_N], g_x3[S3_N], g_z3[S3_N], g_rh3[S3_N];

__device__ __forceinline__ float sigmoidf_(float v) { return 1.f / (1.f + expf(-v)); }

// ---------------------------------------------------------------------------
// Strided conv k4 s2 p1.  Block: 16x16 output pixels, 4 output channels/thread.
// grid = (Wout/16, Hout/16, B * Cout/4)
// ---------------------------------------------------------------------------
__global__ __launch_bounds__(256) void conv4s2_kernel(
    const float* __restrict__ x, long xbstride,
    const float* __restrict__ w, const float* __restrict__ bias,
    float* __restrict__ y, int Cin, int Cout, int Hin, int Win)
{
    const int Hout = Hin >> 1, Wout = Win >> 1;
    const int nog = Cout >> 2;
    const int bx = blockIdx.x, by = blockIdx.y;
    const int ocg = blockIdx.z % nog, bb = blockIdx.z / nog;
    const int tx = threadIdx.x, ty = threadIdx.y;
    const int tid = ty * 16 + tx;
    const int oh = by * 16 + ty, ow = bx * 16 + tx;

    __shared__ float s_in[34 * 34];
    __shared__ float4 s_w4[16];      // [k][4 ocs]

    float acc0 = 0.f, acc1 = 0.f, acc2 = 0.f, acc3 = 0.f;
    const int ih0 = by * 32 - 1, iw0 = bx * 32 - 1;
    const int oc0 = ocg * 4;
    const float* xb = x + (long)bb * xbstride;

    for (int ci = 0; ci < Cin; ci++) {
        const float* xc = xb + (long)ci * Hin * Win;
        for (int i = tid; i < 34 * 34; i += 256) {
            int r = i / 34, c = i - r * 34;
            int ih = ih0 + r, iw = iw0 + c;
            float v = 0.f;
            if ((unsigned)ih < (unsigned)Hin && (unsigned)iw < (unsigned)Win)
                v = xc[ih * Win + iw];
            s_in[i] = v;
        }
        if (tid < 64) {
            int k = tid >> 2, j = tid & 3;
            ((float*)s_w4)[k * 4 + j] = w[((long)(oc0 + j) * Cin + ci) * 16 + k];
        }
        __syncthreads();
        #pragma unroll
        for (int kh = 0; kh < 4; kh++) {
            #pragma unroll
            for (int kw = 0; kw < 4; kw++) {
                float v = s_in[(2 * ty + kh) * 34 + 2 * tx + kw];
                float4 wv = s_w4[kh * 4 + kw];
                acc0 += v * wv.x; acc1 += v * wv.y;
                acc2 += v * wv.z; acc3 += v * wv.w;
            }
        }
        __syncthreads();
    }
    const long cs = (long)Hout * Wout;
    long base = (((long)bb * Cout + oc0) * Hout + oh) * Wout + ow;
    y[base]          = acc0 + bias[oc0];
    y[base + cs]     = acc1 + bias[oc0 + 1];
    y[base + 2 * cs] = acc2 + bias[oc0 + 2];
    y[base + 3 * cs] = acc3 + bias[oc0 + 3];
}

// ---------------------------------------------------------------------------
// ConvGRU gate conv (k5,p2) over concat[x, h]: Cin=2C, Cout=2C.
// Fused epilogue: sigmoid; first C chans -> z buffer, last C -> rh = r*h.
// grid = (W/16, H/16, B * 2C/4)
// ---------------------------------------------------------------------------
__global__ __launch_bounds__(256) void conv5_zr_kernel(
    const float* __restrict__ x, const float* __restrict__ h,
    const float* __restrict__ w, const float* __restrict__ bias,
    float* __restrict__ z, float* __restrict__ rh,
    int C, int H, int W)
{
    const int Cin = 2 * C;
    const int nog = C >> 1;                 // (2C)/4
    const int bx = blockIdx.x, by = blockIdx.y;
    const int ocg = blockIdx.z % nog, bb = blockIdx.z / nog;
    const int tx = threadIdx.x, ty = threadIdx.y;
    const int tid = ty * 16 + tx;
    const int oh = by * 16 + ty, ow = bx * 16 + tx;

    __shared__ float s_in[20 * 20];
    __shared__ float4 s_w4[25];

    float acc0 = 0.f, acc1 = 0.f, acc2 = 0.f, acc3 = 0.f;
    const int ih0 = by * 16 - 2, iw0 = bx * 16 - 2;
    const int oc0 = ocg * 4;
    const long hw = (long)H * W;

    for (int ci = 0; ci < Cin; ci++) {
        const float* src = (ci < C) ? (x + ((long)bb * C + ci) * hw)
                                    : (h + ((long)bb * C + (ci - C)) * hw);
        {
            int i = tid;
            int r = i / 20, c = i - r * 20;
            int ih = ih0 + r, iw = iw0 + c;
            s_in[i] = ((unsigned)ih < (unsigned)H && (unsigned)iw < (unsigned)W)
                      ? src[ih * W + iw] : 0.f;
            i = tid + 256;
            if (i < 400) {
                r = i / 20; c = i - r * 20;
                ih = ih0 + r; iw = iw0 + c;
                s_in[i] = ((unsigned)ih < (unsigned)H && (unsigned)iw < (unsigned)W)
                          ? src[ih * W + iw] : 0.f;
            }
        }
        if (tid < 100) {
            int k = tid >> 2, j = tid & 3;
            ((float*)s_w4)[k * 4 + j] = w[((long)(oc0 + j) * Cin + ci) * 25 + k];
        }
        __syncthreads();
        #pragma unroll
        for (int kh = 0; kh < 5; kh++) {
            #pragma unroll
            for (int kw = 0; kw < 5; kw++) {
                float v = s_in[(ty + kh) * 20 + tx + kw];
                float4 wv = s_w4[kh * 5 + kw];
                acc0 += v * wv.x; acc1 += v * wv.y;
                acc2 += v * wv.z; acc3 += v * wv.w;
            }
        }
        __syncthreads();
    }

    const long pix = (long)oh * W + ow;
    float a[4] = {acc0, acc1, acc2, acc3};
    if (oc0 < C) {
        #pragma unroll
        for (int j = 0; j < 4; j++)
            z[((long)bb * C + oc0 + j) * hw + pix] = sigmoidf_(a[j] + bias[oc0 + j]);
    } else {
        const int c0 = oc0 - C;
        #pragma unroll
        for (int j = 0; j < 4; j++) {
            float s = sigmoidf_(a[j] + bias[oc0 + j]);
            long idx = ((long)bb * C + c0 + j) * hw + pix;
            rh[idx] = s * h[idx];
        }
    }
}

// ---------------------------------------------------------------------------
// ConvGRU candidate conv (k5,p2) over concat[x, r*h]: Cin=2C, Cout=C.
// Fused epilogue: h_new = (1-z)*h + z*tanh(conv+b), in place on h.
// grid = (W/16, H/16, B * C/4)
// ---------------------------------------------------------------------------
__global__ __launch_bounds__(256) void conv5_h_kernel(
    const float* __restrict__ x, const float* __restrict__ rh,
    const float* __restrict__ w, const float* __restrict__ bias,
    const float* __restrict__ z, float* __restrict__ h,
    int C, int H, int W)
{
    const int Cin = 2 * C;
    const int nog = C >> 2;
    const int bx = blockIdx.x, by = blockIdx.y;
    const int ocg = blockIdx.z % nog, bb = blockIdx.z / nog;
    const int tx = threadIdx.x, ty = threadIdx.y;
    const int tid = ty * 16 + tx;
    const int oh = by * 16 + ty, ow = bx * 16 + tx;

    __shared__ float s_in[20 * 20];
    __shared__ float4 s_w4[25];

    float acc0 = 0.f, acc1 = 0.f, acc2 = 0.f, acc3 = 0.f;
    const int ih0 = by * 16 - 2, iw0 = bx * 16 - 2;
    const int oc0 = ocg * 4;
    const long hw = (long)H * W;

    for (int ci = 0; ci < Cin; ci++) {
        const float* src = (ci < C) ? (x + ((long)bb * C + ci) * hw)
                                    : (rh + ((long)bb * C + (ci - C)) * hw);
        {
            int i = tid;
            int r = i / 20, c = i - r * 20;
            int ih = ih0 + r, iw = iw0 + c;
            s_in[i] = ((unsigned)ih < (unsigned)H && (unsigned)iw < (unsigned)W)
                      ? src[ih * W + iw] : 0.f;
            i = tid + 256;
            if (i < 400) {
                r = i / 20; c = i - r * 20;
                ih = ih0 + r; iw = iw0 + c;
                s_in[i] = ((unsigned)ih < (unsigned)H && (unsigned)iw < (unsigned)W)
                          ? src[ih * W + iw] : 0.f;
            }
        }
        if (tid < 100) {
            int k = tid >> 2, j = tid & 3;
            ((float*)s_w4)[k * 4 + j] = w[((long)(oc0 + j) * Cin + ci) * 25 + k];
        }
        __syncthreads();
        #pragma unroll
        for (int kh = 0; kh < 5; kh++) {
            #pragma unroll
            for (int kw = 0; kw < 5; kw++) {
                float v = s_in[(ty + kh) * 20 + tx + kw];
                float4 wv = s_w4[kh * 5 + kw];
                acc0 += v * wv.x; acc1 += v * wv.y;
                acc2 += v * wv.z; acc3 += v * wv.w;
            }
        }
        __syncthreads();
    }

    const long pix = (long)oh * W + ow;
    float a[4] = {acc0, acc1, acc2, acc3};
    #pragma unroll
    for (int j = 0; j < 4; j++) {
        long idx = ((long)bb * C + oc0 + j) * hw + pix;
        float ht = tanhf(a[j] + bias[oc0 + j]);
        float zz = z[idx];
        float hp = h[idx];
        h[idx] = (1.f - zz) * hp + zz * ht;
    }
}

__global__ void copyout_kernel(const float* __restrict__ a, int na,
                               const float* __restrict__ b, int nb,
                               const float* __restrict__ c, int nc,
                               float* __restrict__ out)
{
    int i = blockIdx.x * blockDim.x + threadIdx.x;
    if (i < na) out[i] = a[i];
    else if (i < na + nb) out[i] = b[i - na];
    else if (i < na + nb + nc) out[i] = c[i - na - nb];
}

extern "C" void kernel_launch(void* const* d_in, const int* in_sizes, int n_in,
                              void* d_out, int out_size)
{
    const float* input   = (const float*)d_in[0];
    const float* c1_w    = (const float*)d_in[1];
    const float* c1_b    = (const float*)d_in[2];
    const float* g1_zr_w = (const float*)d_in[3];
    const float* g1_zr_b = (const float*)d_in[4];
    const float* g1_h_w  = (const float*)d_in[5];
    const float* g1_h_b  = (const float*)d_in[6];
    const float* c2_w    = (const float*)d_in[7];
    const float* c2_b    = (const float*)d_in[8];
    const float* g2_zr_w = (const float*)d_in[9];
    const float* g2_zr_b = (const float*)d_in[10];
    const float* g2_h_w  = (const float*)d_in[11];
    const float* g2_h_b  = (const float*)d_in[12];
    const float* c3_w    = (const float*)d_in[13];
    const float* c3_b    = (const float*)d_in[14];
    const float* g3_zr_w = (const float*)d_in[15];
    const float* g3_zr_b = (const float*)d_in[16];
    const float* g3_h_w  = (const float*)d_in[17];
    const float* g3_h_b  = (const float*)d_in[18];

    float *h1, *x1, *z1, *rh1, *h2, *x2, *z2, *rh2, *h3, *x3, *z3, *rh3;
    cudaGetSymbolAddress((void**)&h1,  g_h1);
    cudaGetSymbolAddress((void**)&x1,  g_x1);
    cudaGetSymbolAddress((void**)&z1,  g_z1);
    cudaGetSymbolAddress((void**)&rh1, g_rh1);
    cudaGetSymbolAddress((void**)&h2,  g_h2);
    cudaGetSymbolAddress((void**)&x2,  g_x2);
    cudaGetSymbolAddress((void**)&z2,  g_z2);
    cudaGetSymbolAddress((void**)&rh2, g_rh2);
    cudaGetSymbolAddress((void**)&h3,  g_h3);
    cudaGetSymbolAddress((void**)&x3,  g_x3);
    cudaGetSymbolAddress((void**)&z3,  g_z3);
    cudaGetSymbolAddress((void**)&rh3, g_rh3);

    cudaMemsetAsync(h1, 0, (size_t)S1_N * sizeof(float), 0);
    cudaMemsetAsync(h2, 0, (size_t)S2_N * sizeof(float), 0);
    cudaMemsetAsync(h3, 0, (size_t)S3_N * sizeof(float), 0);

    const dim3 blk(16, 16);
    const long in_bstride = (long)12 * 128 * 128;   // T*H*W, C=1

    for (int t = 0; t < 12; t++) {
        // -------- stage 1 --------
        conv4s2_kernel<<<dim3(4, 4, 8 * 16), blk>>>(
            input + (long)t * 128 * 128, in_bstride, c1_w, c1_b, x1, 1, 64, 128, 128);
        conv5_zr_kernel<<<dim3(4, 4, 8 * 32), blk>>>(
            x1, h1, g1_zr_w, g1_zr_b, z1, rh1, 64, 64, 64);
        conv5_h_kernel<<<dim3(4, 4, 8 * 16), blk>>>(
            x1, rh1, g1_h_w, g1_h_b, z1, h1, 64, 64, 64);
        // -------- stage 2 --------
        conv4s2_kernel<<<dim3(2, 2, 8 * 32), blk>>>(
            h1, (long)64 * 64 * 64, c2_w, c2_b, x2, 64, 128, 64, 64);
        conv5_zr_kernel<<<dim3(2, 2, 8 * 64), blk>>>(
            x2, h2, g2_zr_w, g2_zr_b, z2, rh2, 128, 32, 32);
        conv5_h_kernel<<<dim3(2, 2, 8 * 32), blk>>>(
            x2, rh2, g2_h_w, g2_h_b, z2, h2, 128, 32, 32);
        // -------- stage 3 --------
        conv4s2_kernel<<<dim3(1, 1, 8 * 32), blk>>>(
            h2, (long)128 * 32 * 32, c3_w, c3_b, x3, 128, 128, 32, 32);
        conv5_zr_kernel<<<dim3(1, 1, 8 * 64), blk>>>(
            x3, h3, g3_zr_w, g3_zr_b, z3, rh3, 128, 16, 16);
        conv5_h_kernel<<<dim3(1, 1, 8 * 32), blk>>>(
            x3, rh3, g3_h_w, g3_h_b, z3, h3, 128, 16, 16);
    }

    const int total = S1_N + S2_N + S3_N;
    copyout_kernel<<<(total + 255) / 256, 256>>>(h1, S1_N, h2, S2_N, h3, S3_N,
                                                 (float*)d_out);
}

// round 3
// speedup vs baseline: 1.5718x; 1.5718x over previous
#include <cuda_runtime.h>
#include <math.h>

// ---------------------------------------------------------------------------
// Encoder: 3 stages, each = strided conv (k4,s2,p1) + ConvGRU (k5,p2), T=12, B=8
// f32x2 packed-FMA register-tiled direct convolutions.
// ---------------------------------------------------------------------------

#define S1_N (8*64*64*64)
#define S2_N (8*128*32*32)
#define S3_N (8*128*16*16)

__device__ float g_h1[S1_N], g_x1[S1_N], g_z1[S1_N], g_rh1[S1_N];
__device__ float g_h2[S2_N], g_x2[S2_N], g_z2[S2_N], g_rh2[S2_N];
__device__ float g_h3[S3_N], g_x3[S3_N], g_z3[S3_N], g_rh3[S3_N];

typedef unsigned long long ull;

__device__ __forceinline__ ull pack2(float lo, float hi) {
    ull r; asm("mov.b64 %0, {%1, %2};" : "=l"(r) : "f"(lo), "f"(hi)); return r;
}
__device__ __forceinline__ void unpack2(ull v, float& lo, float& hi) {
    asm("mov.b64 {%0, %1}, %2;" : "=f"(lo), "=f"(hi) : "l"(v));
}
__device__ __forceinline__ ull ffma2(ull a, ull b, ull c) {
    ull d; asm("fma.rn.f32x2 %0, %1, %2, %3;" : "=l"(d) : "l"(a), "l"(b), "l"(c)); return d;
}
__device__ __forceinline__ float sigmoidf_(float v) { return 1.f / (1.f + expf(-v)); }

// ---------------------------------------------------------------------------
// ConvGRU conv (k5,p2), Cin=2C. Per block: 16x16 pixels x 16 oc.
// Thread: 4 horizontal pixels x 4 oc (2 pixel-pairs as f32x2).
// MODE 0 (zr): Cout=2C; sigmoid; z-half -> zbuf, r-half -> outbuf = r * hbuf
// MODE 1 (h):  Cout=C;  hbuf = (1-z)*hbuf + z*tanh(conv)
// grid = (W/16, H/16, B * Cout/16), block = 256
// ---------------------------------------------------------------------------
template<int MODE>
__global__ __launch_bounds__(256) void conv5_kernel(
    const float* __restrict__ x, const float* __restrict__ srcB,
    const float* __restrict__ w, const float* __restrict__ bias,
    float* __restrict__ zbuf, float* __restrict__ hbuf, float* __restrict__ outbuf,
    int C, int H, int W)
{
    const int Cin  = 2 * C;
    const int Cout = (MODE == 0) ? 2 * C : C;
    const int nOcB = Cout >> 4;
    const int bx = blockIdx.x, by = blockIdx.y;
    const int ocB = blockIdx.z % nOcB, bb = blockIdx.z / nOcB;
    const int oc0 = ocB << 4;
    const int tid = threadIdx.x;
    const int tx4 = tid & 3;
    const int ty  = (tid >> 2) & 15;
    const int og4 = (tid >> 6) << 2;          // 0,4,8,12
    const int row  = by * 16 + ty;
    const int col0 = bx * 16 + tx4 * 4;
    const long hw = (long)H * W;

    __shared__ __align__(16) float  s_in[4][400];       // [u][20*20]
    __shared__ __align__(16) float2 s_w2[4 * 25 * 16];  // [u][k][oc], replicated

    // ---- precompute tile-load slots (loop-invariant) ----
    int t_g0, t_g1; bool t_v0, t_v1;
    {
        int p = tid;
        int r = p / 20, c = p - r * 20;
        int ih = by * 16 - 2 + r, iw = bx * 16 - 2 + c;
        t_v0 = ((unsigned)ih < (unsigned)H) && ((unsigned)iw < (unsigned)W);
        t_g0 = ih * W + iw;
        p = tid + 256;
        r = p / 20; c = p - r * 20;
        ih = by * 16 - 2 + r; iw = bx * 16 - 2 + c;
        t_v1 = (p < 400) && ((unsigned)ih < (unsigned)H) && ((unsigned)iw < (unsigned)W);
        t_g1 = ih * W + iw;
    }
    // ---- precompute weight-load slots ----
    int w_g[7]; bool w_act[7];
    #pragma unroll
    for (int s = 0; s < 7; s++) {
        int q = tid + s * 256;
        w_act[s] = q < 1600;
        int u = q / 400; int rem = q - u * 400;
        int k = rem >> 4, j = rem & 15;
        if (u > 3) u = 3;  // keep index sane when inactive
        w_g[s] = ((oc0 + j) * Cin + u) * 25 + k;
    }

    ull acc[2][4];
    #pragma unroll
    for (int pp = 0; pp < 2; pp++)
        #pragma unroll
        for (int j = 0; j < 4; j++) acc[pp][j] = 0ULL;

    const float* xb = x    + (long)bb * C * hw;
    const float* sb = srcB + (long)bb * C * hw;
    const int nB = Cin >> 2;

    for (int cb = 0; cb < nB; cb++) {
        #pragma unroll
        for (int u = 0; u < 4; u++) {
            int ci = cb * 4 + u;
            const float* src = (ci < C) ? (xb + (long)ci * hw)
                                        : (sb + (long)(ci - C) * hw);
            s_in[u][tid] = t_v0 ? src[t_g0] : 0.f;
            if (tid < 144)
                s_in[u][tid + 256] = t_v1 ? src[t_g1] : 0.f;
        }
        #pragma unroll
        for (int s = 0; s < 7; s++) {
            if (w_act[s]) {
                float wv = w[w_g[s] + cb * 100];
                s_w2[tid + s * 256] = make_float2(wv, wv);
            }
        }
        __syncthreads();

        #pragma unroll
        for (int u = 0; u < 4; u++) {
            #pragma unroll
            for (int kh = 0; kh < 5; kh++) {
                const float4* rp = (const float4*)&s_in[u][(ty + kh) * 20 + tx4 * 4];
                float4 ra = rp[0], rb = rp[1];
                float xr[8] = {ra.x, ra.y, ra.z, ra.w, rb.x, rb.y, rb.z, rb.w};
                #pragma unroll
                for (int kw = 0; kw < 5; kw++) {
                    const ulonglong2* wp =
                        (const ulonglong2*)&s_w2[(u * 25 + kh * 5 + kw) * 16 + og4];
                    ulonglong2 wa = wp[0], wb = wp[1];
                    ull v01 = pack2(xr[kw],     xr[kw + 1]);
                    ull v23 = pack2(xr[kw + 2], xr[kw + 3]);
                    acc[0][0] = ffma2(v01, wa.x, acc[0][0]);
                    acc[0][1] = ffma2(v01, wa.y, acc[0][1]);
                    acc[0][2] = ffma2(v01, wb.x, acc[0][2]);
                    acc[0][3] = ffma2(v01, wb.y, acc[0][3]);
                    acc[1][0] = ffma2(v23, wa.x, acc[1][0]);
                    acc[1][1] = ffma2(v23, wa.y, acc[1][1]);
                    acc[1][2] = ffma2(v23, wb.x, acc[1][2]);
                    acc[1][3] = ffma2(v23, wb.y, acc[1][3]);
                }
            }
        }
        __syncthreads();
    }

    float a[4][4];   // [oc j][pixel]
    #pragma unroll
    for (int j = 0; j < 4; j++) {
        unpack2(acc[0][j], a[j][0], a[j][1]);
        unpack2(acc[1][j], a[j][2], a[j][3]);
    }
    const long pixbase = (long)row * W + col0;

    if (MODE == 0) {
        if (oc0 < C) {
            #pragma unroll
            for (int j = 0; j < 4; j++) {
                int oc = oc0 + og4 + j;
                float b = bias[oc];
                float4 o;
                o.x = sigmoidf_(a[j][0] + b); o.y = sigmoidf_(a[j][1] + b);
                o.z = sigmoidf_(a[j][2] + b); o.w = sigmoidf_(a[j][3] + b);
                *(float4*)&zbuf[((long)bb * C + oc) * hw + pixbase] = o;
            }
        } else {
            #pragma unroll
            for (int j = 0; j < 4; j++) {
                int oc = oc0 + og4 + j;
                float b = bias[oc];
                long idx = ((long)bb * C + (oc - C)) * hw + pixbase;
                float4 hv = *(const float4*)&hbuf[idx];
                float4 o;
                o.x = sigmoidf_(a[j][0] + b) * hv.x;
                o.y = sigmoidf_(a[j][1] + b) * hv.y;
                o.z = sigmoidf_(a[j][2] + b) * hv.z;
                o.w = sigmoidf_(a[j][3] + b) * hv.w;
                *(float4*)&outbuf[idx] = o;
            }
        }
    } else {
        #pragma unroll
        for (int j = 0; j < 4; j++) {
            int oc = oc0 + og4 + j;
            float b = bias[oc];
            long idx = ((long)bb * C + oc) * hw + pixbase;
            float4 zv = *(const float4*)&zbuf[idx];
            float4 hv = *(const float4*)&hbuf[idx];
            float4 o;
            o.x = (1.f - zv.x) * hv.x + zv.x * tanhf(a[j][0] + b);
            o.y = (1.f - zv.y) * hv.y + zv.y * tanhf(a[j][1] + b);
            o.z = (1.f - zv.z) * hv.z + zv.z * tanhf(a[j][2] + b);
            o.w = (1.f - zv.w) * hv.w + zv.w * tanhf(a[j][3] + b);
            *(float4*)&hbuf[idx] = o;
        }
    }
}

// ---------------------------------------------------------------------------
// Strided conv k4 s2 p1, Cin even (stages 2/3). 16x16 out pixels x 16 oc/block.
// Thread: 4 pixels x 4 oc, f32x2 packed.
// grid = (Wout/16, Hout/16, B * Cout/16), block = 256
// ---------------------------------------------------------------------------
__global__ __launch_bounds__(256) void conv4s2_kernel(
    const float* __restrict__ x, const float* __restrict__ w,
    const float* __restrict__ bias, float* __restrict__ y,
    int Cin, int Cout, int Hin, int Win)
{
    const int Hout = Hin >> 1, Wout = Win >> 1;
    const int nOcB = Cout >> 4;
    const int bx = blockIdx.x, by = blockIdx.y;
    const int ocB = blockIdx.z % nOcB, bb = blockIdx.z / nOcB;
    const int oc0 = ocB << 4;
    const int tid = threadIdx.x;
    const int tx4 = tid & 3;
    const int ty  = (tid >> 2) & 15;
    const int og4 = (tid >> 6) << 2;
    const int oh  = by * 16 + ty;
    const int ow0 = bx * 16 + tx4 * 4;

    __shared__ __align__(16) float  s_in[2][34 * 36];
    __shared__ __align__(16) float2 s_w2[2 * 16 * 16];

    // tile-load slots: 1224 elems, 5 slots
    int t_g[5]; bool t_v[5];
    #pragma unroll
    for (int s = 0; s < 5; s++) {
        int p = tid + s * 256;
        int r = p / 36, c = p - r * 36;
        int ih = by * 32 - 1 + r, iw = bx * 32 - 1 + c;
        t_v[s] = (p < 1224) && ((unsigned)ih < (unsigned)Hin) &&
                 ((unsigned)iw < (unsigned)Win) && (c < 34);
        t_g[s] = ih * Win + iw;
    }
    // weight slots: 512 scalars, 2 slots
    int w_g[2];
    #pragma unroll
    for (int s = 0; s < 2; s++) {
        int q = tid + s * 256;
        int u = q >> 8; int rem = q & 255;
        int k = rem >> 4, j = rem & 15;
        w_g[s] = ((oc0 + j) * Cin + u) * 16 + k;
    }

    ull acc[2][4];
    #pragma unroll
    for (int pp = 0; pp < 2; pp++)
        #pragma unroll
        for (int j = 0; j < 4; j++) acc[pp][j] = 0ULL;

    const float* xb = x + (long)bb * Cin * Hin * Win;
    const long hwin = (long)Hin * Win;
    const int nB = Cin >> 1;

    for (int cb = 0; cb < nB; cb++) {
        #pragma unroll
        for (int u = 0; u < 2; u++) {
            const float* src = xb + (long)(cb * 2 + u) * hwin;
            #pragma unroll
            for (int s = 0; s < 5; s++) {
                int p = tid + s * 256;
                if (p < 1224)
                    s_in[u][p] = t_v[s] ? src[t_g[s]] : 0.f;
            }
        }
        #pragma unroll
        for (int s = 0; s < 2; s++) {
            float wv = w[w_g[s] + cb * 32];
            s_w2[tid + s * 256] = make_float2(wv, wv);
        }
        __syncthreads();

        #pragma unroll
        for (int u = 0; u < 2; u++) {
            #pragma unroll
            for (int kh = 0; kh < 4; kh++) {
                const float4* rp = (const float4*)&s_in[u][(2 * ty + kh) * 36 + tx4 * 8];
                float4 ra = rp[0], rb = rp[1], rc = rp[2];
                float xr[12] = {ra.x, ra.y, ra.z, ra.w, rb.x, rb.y, rb.z, rb.w,
                                rc.x, rc.y, rc.z, rc.w};
                #pragma unroll
                for (int kw = 0; kw < 4; kw++) {
                    const ulonglong2* wp =
                        (const ulonglong2*)&s_w2[(u * 16 + kh * 4 + kw) * 16 + og4];
                    ulonglong2 wa = wp[0], wb = wp[1];
                    ull v01 = pack2(xr[kw],     xr[kw + 2]);
                    ull v23 = pack2(xr[kw + 4], xr[kw + 6]);
                    acc[0][0] = ffma2(v01, wa.x, acc[0][0]);
                    acc[0][1] = ffma2(v01, wa.y, acc[0][1]);
                    acc[0][2] = ffma2(v01, wb.x, acc[0][2]);
                    acc[0][3] = ffma2(v01, wb.y, acc[0][3]);
                    acc[1][0] = ffma2(v23, wa.x, acc[1][0]);
                    acc[1][1] = ffma2(v23, wa.y, acc[1][1]);
                    acc[1][2] = ffma2(v23, wb.x, acc[1][2]);
                    acc[1][3] = ffma2(v23, wb.y, acc[1][3]);
                }
            }
        }
        __syncthreads();
    }

    const long hwout = (long)Hout * Wout;
    #pragma unroll
    for (int j = 0; j < 4; j++) {
        int oc = oc0 + og4 + j;
        float b = bias[oc];
        float p0, p1, p2, p3;
        unpack2(acc[0][j], p0, p1);
        unpack2(acc[1][j], p2, p3);
        float4 o = make_float4(p0 + b, p1 + b, p2 + b, p3 + b);
        *(float4*)&y[((long)bb * Cout + oc) * hwout + (long)oh * Wout + ow0] = o;
    }
}

// ---------------------------------------------------------------------------
// Stage-1 strided conv (Cin=1): simple version, negligible cost.
// grid = (4, 4, B * Cout/4), block = (16,16)
// ---------------------------------------------------------------------------
__global__ __launch_bounds__(256) void conv4s2_c1_kernel(
    const float* __restrict__ x, long xbstride,
    const float* __restrict__ w, const float* __restrict__ bias,
    float* __restrict__ y, int Cout, int Hin, int Win)
{
    const int Hout = Hin >> 1, Wout = Win >> 1;
    const int nog = Cout >> 2;
    const int bx = blockIdx.x, by = blockIdx.y;
    const int ocg = blockIdx.z % nog, bb = blockIdx.z / nog;
    const int tx = threadIdx.x, ty = threadIdx.y;
    const int tid = ty * 16 + tx;
    const int oh = by * 16 + ty, ow = bx * 16 + tx;

    __shared__ float s_in[34 * 34];
    __shared__ float4 s_w4[16];

    float acc0 = 0.f, acc1 = 0.f, acc2 = 0.f, acc3 = 0.f;
    const int ih0 = by * 32 - 1, iw0 = bx * 32 - 1;
    const int oc0 = ocg * 4;
    const float* xc = x + (long)bb * xbstride;

    for (int i = tid; i < 34 * 34; i += 256) {
        int r = i / 34, c = i - r * 34;
        int ih = ih0 + r, iw = iw0 + c;
        float v = 0.f;
        if ((unsigned)ih < (unsigned)Hin && (unsigned)iw < (unsigned)Win)
            v = xc[ih * Win + iw];
        s_in[i] = v;
    }
    if (tid < 64) {
        int k = tid >> 2, j = tid & 3;
        ((float*)s_w4)[k * 4 + j] = w[(oc0 + j) * 16 + k];
    }
    __syncthreads();
    #pragma unroll
    for (int kh = 0; kh < 4; kh++) {
        #pragma unroll
        for (int kw = 0; kw < 4; kw++) {
            float v = s_in[(2 * ty + kh) * 34 + 2 * tx + kw];
            float4 wv = s_w4[kh * 4 + kw];
            acc0 += v * wv.x; acc1 += v * wv.y;
            acc2 += v * wv.z; acc3 += v * wv.w;
        }
    }
    const long cs = (long)Hout * Wout;
    long base = (((long)bb * Cout + oc0) * Hout + oh) * Wout + ow;
    y[base]          = acc0 + bias[oc0];
    y[base + cs]     = acc1 + bias[oc0 + 1];
    y[base + 2 * cs] = acc2 + bias[oc0 + 2];
    y[base + 3 * cs] = acc3 + bias[oc0 + 3];
}

__global__ void copyout_kernel(const float* __restrict__ a, int na,
                               const float* __restrict__ b, int nb,
                               const float* __restrict__ c, int nc,
                               float* __restrict__ out)
{
    int i = blockIdx.x * blockDim.x + threadIdx.x;
    if (i < na) out[i] = a[i];
    else if (i < na + nb) out[i] = b[i - na];
    else if (i < na + nb + nc) out[i] = c[i - na - nb];
}

extern "C" void kernel_launch(void* const* d_in, const int* in_sizes, int n_in,
                              void* d_out, int out_size)
{
    const float* input   = (const float*)d_in[0];
    const float* c1_w    = (const float*)d_in[1];
    const float* c1_b    = (const float*)d_in[2];
    const float* g1_zr_w = (const float*)d_in[3];
    const float* g1_zr_b = (const float*)d_in[4];
    const float* g1_h_w  = (const float*)d_in[5];
    const float* g1_h_b  = (const float*)d_in[6];
    const float* c2_w    = (const float*)d_in[7];
    const float* c2_b    = (const float*)d_in[8];
    const float* g2_zr_w = (const float*)d_in[9];
    const float* g2_zr_b = (const float*)d_in[10];
    const float* g2_h_w  = (const float*)d_in[11];
    const float* g2_h_b  = (const float*)d_in[12];
    const float* c3_w    = (const float*)d_in[13];
    const float* c3_b    = (const float*)d_in[14];
    const float* g3_zr_w = (const float*)d_in[15];
    const float* g3_zr_b = (const float*)d_in[16];
    const float* g3_h_w  = (const float*)d_in[17];
    const float* g3_h_b  = (const float*)d_in[18];

    float *h1, *x1, *z1, *rh1, *h2, *x2, *z2, *rh2, *h3, *x3, *z3, *rh3;
    cudaGetSymbolAddress((void**)&h1,  g_h1);
    cudaGetSymbolAddress((void**)&x1,  g_x1);
    cudaGetSymbolAddress((void**)&z1,  g_z1);
    cudaGetSymbolAddress((void**)&rh1, g_rh1);
    cudaGetSymbolAddress((void**)&h2,  g_h2);
    cudaGetSymbolAddress((void**)&x2,  g_x2);
    cudaGetSymbolAddress((void**)&z2,  g_z2);
    cudaGetSymbolAddress((void**)&rh2, g_rh2);
    cudaGetSymbolAddress((void**)&h3,  g_h3);
    cudaGetSymbolAddress((void**)&x3,  g_x3);
    cudaGetSymbolAddress((void**)&z3,  g_z3);
    cudaGetSymbolAddress((void**)&rh3, g_rh3);

    cudaMemsetAsync(h1, 0, (size_t)S1_N * sizeof(float), 0);
    cudaMemsetAsync(h2, 0, (size_t)S2_N * sizeof(float), 0);
    cudaMemsetAsync(h3, 0, (size_t)S3_N * sizeof(float), 0);

    const long in_bstride = (long)12 * 128 * 128;   // T*H*W (C=1)

    for (int t = 0; t < 12; t++) {
        // -------- stage 1 --------
        conv4s2_c1_kernel<<<dim3(4, 4, 8 * 16), dim3(16, 16)>>>(
            input + (long)t * 128 * 128, in_bstride, c1_w, c1_b, x1, 64, 128, 128);
        conv5_kernel<0><<<dim3(4, 4, 8 * 8), 256>>>(
            x1, h1, g1_zr_w, g1_zr_b, z1, h1, rh1, 64, 64, 64);
        conv5_kernel<1><<<dim3(4, 4, 8 * 4), 256>>>(
            x1, rh1, g1_h_w, g1_h_b, z1, h1, nullptr, 64, 64, 64);
        // -------- stage 2 --------
        conv4s2_kernel<<<dim3(2, 2, 8 * 8), 256>>>(
            h1, c2_w, c2_b, x2, 64, 128, 64, 64);
        conv5_kernel<0><<<dim3(2, 2, 8 * 16), 256>>>(
            x2, h2, g2_zr_w, g2_zr_b, z2, h2, rh2, 128, 32, 32);
        conv5_kernel<1><<<dim3(2, 2, 8 * 8), 256>>>(
            x2, rh2, g2_h_w, g2_h_b, z2, h2, nullptr, 128, 32, 32);
        // -------- stage 3 --------
        conv4s2_kernel<<<dim3(1, 1, 8 * 8), 256>>>(
            h2, c3_w, c3_b, x3, 128, 128, 32, 32);
        conv5_kernel<0><<<dim3(1, 1, 8 * 16), 256>>>(
            x3, h3, g3_zr_w, g3_zr_b, z3, h3, rh3, 128, 16, 16);
        conv5_kernel<1><<<dim3(1, 1, 8 * 8), 256>>>(
            x3, rh3, g3_h_w, g3_h_b, z3, h3, nullptr, 128, 16, 16);
    }

    const int total = S1_N + S2_N + S3_N;
    copyout_kernel<<<(total + 255) / 256, 256>>>(h1, S1_N, h2, S2_N, h3, S3_N,
                                                 (float*)d_out);
}

// round 4
// speedup vs baseline: 2.4764x; 1.5755x over previous
#include <cuda_runtime.h>
#include <math.h>
#include <stdint.h>

// ---------------------------------------------------------------------------
// Encoder: 3 stages (conv k4s2p1 + ConvGRU k5p2), T=12, B=8.
// cp.async double-buffered, f32x2 packed-FMA (oc-paired), register-tiled.
// ---------------------------------------------------------------------------

#define S1_N (8*64*64*64)
#define S2_N (8*128*32*32)
#define S3_N (8*128*16*16)

__device__ float g_h1[S1_N], g_x1[S1_N], g_z1[S1_N], g_rh1[S1_N];
__device__ float g_h2[S2_N], g_x2[S2_N], g_z2[S2_N], g_rh2[S2_N];
__device__ float g_h3[S3_N], g_x3[S3_N], g_z3[S3_N], g_rh3[S3_N];

typedef unsigned long long ull;

__device__ __forceinline__ ull pack2(float lo, float hi) {
    ull r; asm("mov.b64 %0, {%1, %2};" : "=l"(r) : "f"(lo), "f"(hi)); return r;
}
__device__ __forceinline__ void unpack2(ull v, float& lo, float& hi) {
    asm("mov.b64 {%0, %1}, %2;" : "=f"(lo), "=f"(hi) : "l"(v));
}
__device__ __forceinline__ ull ffma2(ull a, ull b, ull c) {
    ull d; asm("fma.rn.f32x2 %0, %1, %2, %3;" : "=l"(d) : "l"(a), "l"(b), "l"(c)); return d;
}
__device__ __forceinline__ float sigmoidf_(float v) { return 1.f / (1.f + expf(-v)); }

__device__ __forceinline__ void cp4(uint32_t dst, const float* src, bool p) {
    int sz = p ? 4 : 0;
    asm volatile("cp.async.ca.shared.global [%0], [%1], 4, %2;\n"
                 :: "r"(dst), "l"(src), "r"(sz));
}
__device__ __forceinline__ void cp_commit() { asm volatile("cp.async.commit_group;\n"); }
template<int N> __device__ __forceinline__ void cp_wait() {
    asm volatile("cp.async.wait_group %0;\n" :: "n"(N));
}

// ---------------------------------------------------------------------------
// ConvGRU conv (k5,p2), Cin=2C. Block: 16x16 pixels x OCB oc (OCB = 4*G).
// Thread: 4 horizontal pixels x 4 oc; f32x2 lanes pair ADJACENT OCs so weight
// pairs load straight from smem; pixel values replicated via hoisted packs.
// MODE 0 (zr): Cout=2C; sigmoid; z-half -> zbuf, r-half -> outbuf = r * hbuf
// MODE 1 (h):  Cout=C;  hbuf = (1-z)*hbuf + z*tanh(conv)
// grid = (W/16, H/16, B * Cout/OCB), block = 64*G
// ---------------------------------------------------------------------------
template<int MODE, int G>
__global__ __launch_bounds__(64 * G, (G == 4) ? 3 : 6) void conv5_kernel(
    const float* __restrict__ x, const float* __restrict__ srcB,
    const float* __restrict__ w, const float* __restrict__ bias,
    float* __restrict__ zbuf, float* __restrict__ hbuf, float* __restrict__ outbuf,
    int C, int H, int W)
{
    constexpr int NT   = 64 * G;
    constexpr int OCB  = 4 * G;
    constexpr int TILE = 1600;              // 4 channels * 400 (20x20 halo tile)
    constexpr int TS   = (TILE + NT - 1) / NT;
    constexpr int WW   = 100 * OCB;         // 4ch * 25k * OCB
    constexpr int WS   = (WW + NT - 1) / NT;
    constexpr int PUK  = 25 * OCB;

    const int Cin  = 2 * C;
    const int nOcB = ((MODE == 0) ? 2 * C : C) / OCB;
    const int bx = blockIdx.x, by = blockIdx.y;
    const int ocB = blockIdx.z % nOcB, bb = blockIdx.z / nOcB;
    const int oc0 = ocB * OCB;
    const int tid = threadIdx.x;
    const int tx4 = tid & 3;
    const int ty  = (tid >> 2) & 15;
    const int og4 = (tid >> 6) << 2;
    const int row = by * 16 + ty, col0 = bx * 16 + tx4 * 4;
    const int hw  = H * W;

    __shared__ float s_in[2][TILE];
    __shared__ float s_w[2][WW];
    const uint32_t sin0 = (uint32_t)__cvta_generic_to_shared(&s_in[0][0]);
    const uint32_t sw0  = (uint32_t)__cvta_generic_to_shared(&s_w[0][0]);

    int t_src[TS];
    #pragma unroll
    for (int s = 0; s < TS; s++) {
        int idx = tid + s * NT;
        int u = idx / 400, pos = idx - u * 400;
        int r = pos / 20, c = pos - r * 20;
        int ih = by * 16 - 2 + r, iw = bx * 16 - 2 + c;
        bool v = (idx < TILE) && ((unsigned)ih < (unsigned)H) &&
                 ((unsigned)iw < (unsigned)W);
        t_src[s] = v ? (u * hw + ih * W + iw) : -1;
    }
    int w_gp[WS];
    #pragma unroll
    for (int s = 0; s < WS; s++) {
        int idx = tid + s * NT;
        int u = idx / PUK, rem = idx - u * PUK;
        int k = rem / OCB, j = rem % OCB;
        if (u > 3) u = 3;
        w_gp[s] = ((oc0 + j) * Cin + u) * 25 + k;
    }

    const float* xb  = x    + (long)bb * C * hw;
    const float* sbp = srcB + (long)bb * C * hw;
    const int nB = Cin >> 2;

    auto issue = [&](int cb, int buf) {
        const float* base = (cb * 4 < C) ? (xb + (long)(cb * 4) * hw)
                                         : (sbp + (long)(cb * 4 - C) * hw);
        #pragma unroll
        for (int s = 0; s < TS; s++) {
            if ((s + 1) * NT <= TILE || tid + s * NT < TILE) {
                int so = t_src[s];
                cp4(sin0 + (uint32_t)(buf * TILE + tid + s * NT) * 4,
                    base + (so < 0 ? 0 : so), so >= 0);
            }
        }
        const float* wb = w + cb * 100;
        #pragma unroll
        for (int s = 0; s < WS; s++) {
            if ((s + 1) * NT <= WW || tid + s * NT < WW)
                cp4(sw0 + (uint32_t)(buf * WW + tid + s * NT) * 4,
                    wb + w_gp[s], true);
        }
        cp_commit();
    };

    ull acc0[4], acc1[4];
    #pragma unroll
    for (int p = 0; p < 4; p++) { acc0[p] = 0ULL; acc1[p] = 0ULL; }

    issue(0, 0);
    for (int cb = 0; cb < nB; cb++) {
        const int buf = cb & 1;
        if (cb + 1 < nB) { issue(cb + 1, buf ^ 1); cp_wait<1>(); }
        else cp_wait<0>();
        __syncthreads();

        #pragma unroll
        for (int u = 0; u < 4; u++) {
            #pragma unroll
            for (int kh = 0; kh < 5; kh++) {
                const float4* rp =
                    (const float4*)&s_in[buf][u * 400 + (ty + kh) * 20 + tx4 * 4];
                float4 ra = rp[0], rb = rp[1];
                float xr[8] = {ra.x, ra.y, ra.z, ra.w, rb.x, rb.y, rb.z, rb.w};
                ull vx[8];
                #pragma unroll
                for (int m = 0; m < 8; m++) vx[m] = pack2(xr[m], xr[m]);
                #pragma unroll
                for (int kw = 0; kw < 5; kw++) {
                    ulonglong2 wv = *(const ulonglong2*)
                        &s_w[buf][u * PUK + (kh * 5 + kw) * OCB + og4];
                    #pragma unroll
                    for (int px = 0; px < 4; px++) {
                        acc0[px] = ffma2(wv.x, vx[kw + px], acc0[px]);
                        acc1[px] = ffma2(wv.y, vx[kw + px], acc1[px]);
                    }
                }
            }
        }
        __syncthreads();
    }

    float a[4][4];   // [oc j][px]
    #pragma unroll
    for (int px = 0; px < 4; px++) {
        unpack2(acc0[px], a[0][px], a[1][px]);
        unpack2(acc1[px], a[2][px], a[3][px]);
    }
    const long pix = (long)row * W + col0;

    if (MODE == 0) {
        if (oc0 < C) {
            #pragma unroll
            for (int j = 0; j < 4; j++) {
                int oc = oc0 + og4 + j;
                float b = bias[oc];
                float4 o;
                o.x = sigmoidf_(a[j][0] + b); o.y = sigmoidf_(a[j][1] + b);
                o.z = sigmoidf_(a[j][2] + b); o.w = sigmoidf_(a[j][3] + b);
                *(float4*)&zbuf[((long)bb * C + oc) * hw + pix] = o;
            }
        } else {
            #pragma unroll
            for (int j = 0; j < 4; j++) {
                int oc = oc0 + og4 + j;
                float b = bias[oc];
                long idx = ((long)bb * C + (oc - C)) * hw + pix;
                float4 hv = *(const float4*)&hbuf[idx];
                float4 o;
                o.x = sigmoidf_(a[j][0] + b) * hv.x;
                o.y = sigmoidf_(a[j][1] + b) * hv.y;
                o.z = sigmoidf_(a[j][2] + b) * hv.z;
                o.w = sigmoidf_(a[j][3] + b) * hv.w;
                *(float4*)&outbuf[idx] = o;
            }
        }
    } else {
        #pragma unroll
        for (int j = 0; j < 4; j++) {
            int oc = oc0 + og4 + j;
            float b = bias[oc];
            long idx = ((long)bb * C + oc) * hw + pix;
            float4 zv = *(const float4*)&zbuf[idx];
            float4 hv = *(const float4*)&hbuf[idx];
            float4 o;
            o.x = (1.f - zv.x) * hv.x + zv.x * tanhf(a[j][0] + b);
            o.y = (1.f - zv.y) * hv.y + zv.y * tanhf(a[j][1] + b);
            o.z = (1.f - zv.z) * hv.z + zv.z * tanhf(a[j][2] + b);
            o.w = (1.f - zv.w) * hv.w + zv.w * tanhf(a[j][3] + b);
            *(float4*)&hbuf[idx] = o;
        }
    }
}

// ---------------------------------------------------------------------------
// Strided conv k4 s2 p1 (stages 2/3): 16x16 out px x 16 oc/block, pipelined.
// grid = (Wout/16, Hout/16, B * Cout/16), block = 256
// ---------------------------------------------------------------------------
__global__ __launch_bounds__(256, 3) void conv4s2_kernel(
    const float* __restrict__ x, const float* __restrict__ w,
    const float* __restrict__ bias, float* __restrict__ y,
    int Cin, int Cout, int Hin, int Win)
{
    constexpr int NT = 256, TILE = 2448, TS = 10, WW = 512, WS = 2;
    const int Hout = Hin >> 1, Wout = Win >> 1;
    const int nOcB = Cout >> 4;
    const int bx = blockIdx.x, by = blockIdx.y;
    const int ocB = blockIdx.z % nOcB, bb = blockIdx.z / nOcB;
    const int oc0 = ocB << 4;
    const int tid = threadIdx.x;
    const int tx4 = tid & 3;
    const int ty  = (tid >> 2) & 15;
    const int og4 = (tid >> 6) << 2;
    const int oh = by * 16 + ty, ow0 = bx * 16 + tx4 * 4;
    const int hwin = Hin * Win;

    __shared__ float s_in[2][TILE];
    __shared__ float s_w[2][WW];
    const uint32_t sin0 = (uint32_t)__cvta_generic_to_shared(&s_in[0][0]);
    const uint32_t sw0  = (uint32_t)__cvta_generic_to_shared(&s_w[0][0]);

    int t_src[TS];
    #pragma unroll
    for (int s = 0; s < TS; s++) {
        int idx = tid + s * NT;
        int u = idx / 1224, pos = idx - u * 1224;
        int r = pos / 36, c = pos - r * 36;
        int ih = by * 32 - 1 + r, iw = bx * 32 - 1 + c;
        bool v = (idx < TILE) && (c < 34) && ((unsigned)ih < (unsigned)Hin) &&
                 ((unsigned)iw < (unsigned)Win);
        t_src[s] = v ? (u * hwin + ih * Win + iw) : -1;
    }
    int w_gp[WS];
    #pragma unroll
    for (int s = 0; s < WS; s++) {
        int idx = tid + s * NT;
        int u = idx >> 8, rem = idx & 255;
        int k = rem >> 4, j = rem & 15;
        w_gp[s] = ((oc0 + j) * Cin + u) * 16 + k;
    }

    const float* xb = x + (long)bb * Cin * hwin;
    const int nB = Cin >> 1;

    auto issue = [&](int cb, int buf) {
        const float* base = xb + (long)(cb * 2) * hwin;
        #pragma unroll
        for (int s = 0; s < TS; s++) {
            if ((s + 1) * NT <= TILE || tid + s * NT < TILE) {
                int so = t_src[s];
                cp4(sin0 + (uint32_t)(buf * TILE + tid + s * NT) * 4,
                    base + (so < 0 ? 0 : so), so >= 0);
            }
        }
        const float* wb = w + cb * 32;
        #pragma unroll
        for (int s = 0; s < WS; s++)
            cp4(sw0 + (uint32_t)(buf * WW + tid + s * NT) * 4, wb + w_gp[s], true);
        cp_commit();
    };

    ull acc0[4], acc1[4];
    #pragma unroll
    for (int p = 0; p < 4; p++) { acc0[p] = 0ULL; acc1[p] = 0ULL; }

    issue(0, 0);
    for (int cb = 0; cb < nB; cb++) {
        const int buf = cb & 1;
        if (cb + 1 < nB) { issue(cb + 1, buf ^ 1); cp_wait<1>(); }
        else cp_wait<0>();
        __syncthreads();

        #pragma unroll
        for (int u = 0; u < 2; u++) {
            #pragma unroll
            for (int kh = 0; kh < 4; kh++) {
                const float4* rp = (const float4*)
                    &s_in[buf][u * 1224 + (2 * ty + kh) * 36 + tx4 * 8];
                float4 ra = rp[0], rb = rp[1], rc = rp[2];
                float xr[12] = {ra.x, ra.y, ra.z, ra.w, rb.x, rb.y, rb.z, rb.w,
                                rc.x, rc.y, rc.z, rc.w};
                ull vx[10];
                #pragma unroll
                for (int m = 0; m < 10; m++) vx[m] = pack2(xr[m], xr[m]);
                #pragma unroll
                for (int kw = 0; kw < 4; kw++) {
                    ulonglong2 wv = *(const ulonglong2*)
                        &s_w[buf][u * 256 + (kh * 4 + kw) * 16 + og4];
                    #pragma unroll
                    for (int px = 0; px < 4; px++) {
                        acc0[px] = ffma2(wv.x, vx[2 * px + kw], acc0[px]);
                        acc1[px] = ffma2(wv.y, vx[2 * px + kw], acc1[px]);
                    }
                }
            }
        }
        __syncthreads();
    }

    float a[4][4];
    #pragma unroll
    for (int px = 0; px < 4; px++) {
        unpack2(acc0[px], a[0][px], a[1][px]);
        unpack2(acc1[px], a[2][px], a[3][px]);
    }
    const long hwout = (long)Hout * Wout;
    #pragma unroll
    for (int j = 0; j < 4; j++) {
        int oc = oc0 + og4 + j;
        float b = bias[oc];
        float4 o = make_float4(a[j][0] + b, a[j][1] + b, a[j][2] + b, a[j][3] + b);
        *(float4*)&y[((long)bb * Cout + oc) * hwout + (long)oh * Wout + ow0] = o;
    }
}

// ---------------------------------------------------------------------------
// Stage-1 strided conv (Cin=1): negligible cost, simple version.
// ---------------------------------------------------------------------------
__global__ __launch_bounds__(256) void conv4s2_c1_kernel(
    const float* __restrict__ x, long xbstride,
    const float* __restrict__ w, const float* __restrict__ bias,
    float* __restrict__ y, int Cout, int Hin, int Win)
{
    const int Hout = Hin >> 1, Wout = Win >> 1;
    const int nog = Cout >> 2;
    const int bx = blockIdx.x, by = blockIdx.y;
    const int ocg = blockIdx.z % nog, bb = blockIdx.z / nog;
    const int tx = threadIdx.x, ty = threadIdx.y;
    const int tid = ty * 16 + tx;
    const int oh = by * 16 + ty, ow = bx * 16 + tx;

    __shared__ float s_in[34 * 34];
    __shared__ float4 s_w4[16];

    float acc0 = 0.f, acc1 = 0.f, acc2 = 0.f, acc3 = 0.f;
    const int ih0 = by * 32 - 1, iw0 = bx * 32 - 1;
    const int oc0 = ocg * 4;
    const float* xc = x + (long)bb * xbstride;

    for (int i = tid; i < 34 * 34; i += 256) {
        int r = i / 34, c = i - r * 34;
        int ih = ih0 + r, iw = iw0 + c;
        float v = 0.f;
        if ((unsigned)ih < (unsigned)Hin && (unsigned)iw < (unsigned)Win)
            v = xc[ih * Win + iw];
        s_in[i] = v;
    }
    if (tid < 64) {
        int k = tid >> 2, j = tid & 3;
        ((float*)s_w4)[k * 4 + j] = w[(oc0 + j) * 16 + k];
    }
    __syncthreads();
    #pragma unroll
    for (int kh = 0; kh < 4; kh++) {
        #pragma unroll
        for (int kw = 0; kw < 4; kw++) {
            float v = s_in[(2 * ty + kh) * 34 + 2 * tx + kw];
            float4 wv = s_w4[kh * 4 + kw];
            acc0 += v * wv.x; acc1 += v * wv.y;
            acc2 += v * wv.z; acc3 += v * wv.w;
        }
    }
    const long cs = (long)Hout * Wout;
    long base = (((long)bb * Cout + oc0) * Hout + oh) * Wout + ow;
    y[base]          = acc0 + bias[oc0];
    y[base + cs]     = acc1 + bias[oc0 + 1];
    y[base + 2 * cs] = acc2 + bias[oc0 + 2];
    y[base + 3 * cs] = acc3 + bias[oc0 + 3];
}

__global__ void copyout_kernel(const float* __restrict__ a, int na,
                               const float* __restrict__ b, int nb,
                               const float* __restrict__ c, int nc,
                               float* __restrict__ out)
{
    int i = blockIdx.x * blockDim.x + threadIdx.x;
    if (i < na) out[i] = a[i];
    else if (i < na + nb) out[i] = b[i - na];
    else if (i < na + nb + nc) out[i] = c[i - na - nb];
}

extern "C" void kernel_launch(void* const* d_in, const int* in_sizes, int n_in,
                              void* d_out, int out_size)
{
    const float* input   = (const float*)d_in[0];
    const float* c1_w    = (const float*)d_in[1];
    const float* c1_b    = (const float*)d_in[2];
    const float* g1_zr_w = (const float*)d_in[3];
    const float* g1_zr_b = (const float*)d_in[4];
    const float* g1_h_w  = (const float*)d_in[5];
    const float* g1_h_b  = (const float*)d_in[6];
    const float* c2_w    = (const float*)d_in[7];
    const float* c2_b    = (const float*)d_in[8];
    const float* g2_zr_w = (const float*)d_in[9];
    const float* g2_zr_b = (const float*)d_in[10];
    const float* g2_h_w  = (const float*)d_in[11];
    const float* g2_h_b  = (const float*)d_in[12];
    const float* c3_w    = (const float*)d_in[13];
    const float* c3_b    = (const float*)d_in[14];
    const float* g3_zr_w = (const float*)d_in[15];
    const float* g3_zr_b = (const float*)d_in[16];
    const float* g3_h_w  = (const float*)d_in[17];
    const float* g3_h_b  = (const float*)d_in[18];

    float *h1, *x1, *z1, *rh1, *h2, *x2, *z2, *rh2, *h3, *x3, *z3, *rh3;
    cudaGetSymbolAddress((void**)&h1,  g_h1);
    cudaGetSymbolAddress((void**)&x1,  g_x1);
    cudaGetSymbolAddress((void**)&z1,  g_z1);
    cudaGetSymbolAddress((void**)&rh1, g_rh1);
    cudaGetSymbolAddress((void**)&h2,  g_h2);
    cudaGetSymbolAddress((void**)&x2,  g_x2);
    cudaGetSymbolAddress((void**)&z2,  g_z2);
    cudaGetSymbolAddress((void**)&rh2, g_rh2);
    cudaGetSymbolAddress((void**)&h3,  g_h3);
    cudaGetSymbolAddress((void**)&x3,  g_x3);
    cudaGetSymbolAddress((void**)&z3,  g_z3);
    cudaGetSymbolAddress((void**)&rh3, g_rh3);

    cudaMemsetAsync(h1, 0, (size_t)S1_N * sizeof(float), 0);
    cudaMemsetAsync(h2, 0, (size_t)S2_N * sizeof(float), 0);
    cudaMemsetAsync(h3, 0, (size_t)S3_N * sizeof(float), 0);

    const long in_bstride = (long)12 * 128 * 128;   // T*H*W (C=1)

    for (int t = 0; t < 12; t++) {
        // -------- stage 1 --------
        conv4s2_c1_kernel<<<dim3(4, 4, 8 * 16), dim3(16, 16)>>>(
            input + (long)t * 128 * 128, in_bstride, c1_w, c1_b, x1, 64, 128, 128);
        conv5_kernel<0, 4><<<dim3(4, 4, 8 * 8), 256>>>(
            x1, h1, g1_zr_w, g1_zr_b, z1, h1, rh1, 64, 64, 64);
        conv5_kernel<1, 4><<<dim3(4, 4, 8 * 4), 256>>>(
            x1, rh1, g1_h_w, g1_h_b, z1, h1, nullptr, 64, 64, 64);
        // -------- stage 2 --------
        conv4s2_kernel<<<dim3(2, 2, 8 * 8), 256>>>(
            h1, c2_w, c2_b, x2, 64, 128, 64, 64);
        conv5_kernel<0, 4><<<dim3(2, 2, 8 * 16), 256>>>(
            x2, h2, g2_zr_w, g2_zr_b, z2, h2, rh2, 128, 32, 32);
        conv5_kernel<1, 2><<<dim3(2, 2, 8 * 16), 128>>>(
            x2, rh2, g2_h_w, g2_h_b, z2, h2, nullptr, 128, 32, 32);
        // -------- stage 3 --------
        conv4s2_kernel<<<dim3(1, 1, 8 * 8), 256>>>(
            h2, c3_w, c3_b, x3, 128, 128, 32, 32);
        conv5_kernel<0, 2><<<dim3(1, 1, 8 * 32), 128>>>(
            x3, h3, g3_zr_w, g3_zr_b, z3, h3, rh3, 128, 16, 16);
        conv5_kernel<1, 2><<<dim3(1, 1, 8 * 16), 128>>>(
            x3, rh3, g3_h_w, g3_h_b, z3, h3, nullptr, 128, 16, 16);
    }

    const int total = S1_N + S2_N + S3_N;
    copyout_kernel<<<(total + 255) / 256, 256>>>(h1, S1_N, h2, S2_N, h3, S3_N,
                                                 (float*)d_out);
}